// round 4
// baseline (speedup 1.0000x reference)
#include <cuda_runtime.h>
#include <cuda_fp16.h>

#define NUM_DRUG 50000
#define NUM_CELL 20000
#define HDIM     128
#define NEDGE    600000
#define NBATCH   4096

#define G8_DRUG (NUM_DRUG / 8)   // 6250 warp-groups (divides exactly)
#define G8_CELL (NUM_CELL / 8)   // 2500

#define LAYER_BLOCKS 296
#define ND_BLOCKS    172         // blocks assigned to the drug side
#define WARPS        8           // 256 threads / block
#define LAYER_SMEM ((HDIM * HDIM + WARPS * 8 * HDIM) * sizeof(float))  // 96 KB

// ---------------- scratch (device globals; no runtime allocation) ----------
__device__ __align__(16) float g_hA_drug[NUM_DRUG * HDIM];
__device__ __align__(16) float g_hA_cell[NUM_CELL * HDIM];
__device__ __align__(16) float g_hB_drug[NUM_DRUG * HDIM];
__device__ __align__(16) float g_hB_cell[NUM_CELL * HDIM];
__device__ __align__(16) __half g_he_drug[NUM_DRUG * HDIM];  // fp16 gather tables
__device__ __align__(16) __half g_he_cell[NUM_CELL * HDIM];
__device__ __align__(16) __half g_h1_drug[NUM_DRUG * HDIM];
__device__ __align__(16) __half g_h1_cell[NUM_CELL * HDIM];
__device__ __align__(16) float g_WT_td[HDIM * HDIM];
__device__ __align__(16) float g_WT_dt[HDIM * HDIM];
__device__ int g_off_drug[NUM_DRUG + 1];
__device__ int g_off_cell[NUM_CELL + 1];
__device__ int g_cur_drug[NUM_DRUG];
__device__ int g_cur_cell[NUM_CELL];
__device__ int g_csr_td[NEDGE];   // per drug-dst: source cell ids
__device__ int g_csr_dt[NEDGE];   // per cell-dst: source drug ids

// ---------------- f32x2 helpers --------------------------------------------
__device__ __forceinline__ unsigned long long splat2(float x) {
    unsigned long long r; unsigned xi = __float_as_uint(x);
    asm("mov.b64 %0, {%1, %1};" : "=l"(r) : "r"(xi));
    return r;
}
__device__ __forceinline__ unsigned long long fma2(unsigned long long a,
                                                   unsigned long long b,
                                                   unsigned long long c) {
    unsigned long long d;
    asm("fma.rn.f32x2 %0, %1, %2, %3;" : "=l"(d) : "l"(a), "l"(b), "l"(c));
    return d;
}
__device__ __forceinline__ float lo2(unsigned long long v) {
    return __uint_as_float((unsigned)(v & 0xffffffffull));
}
__device__ __forceinline__ float hi2(unsigned long long v) {
    return __uint_as_float((unsigned)(v >> 32));
}

// accumulate a uint2 (4 halves) into a float4
__device__ __forceinline__ void acc_h4(float4& a, uint2 v) {
    float2 f0 = __half22float2(*reinterpret_cast<__half2*>(&v.x));
    float2 f1 = __half22float2(*reinterpret_cast<__half2*>(&v.y));
    a.x += f0.x; a.y += f0.y; a.z += f1.x; a.w += f1.y;
}

// ---------------- CSR build (both relations in single launches) ------------
__global__ void hist2_kernel(const int* __restrict__ dstA, int* __restrict__ cntA,
                             const int* __restrict__ dstB, int* __restrict__ cntB)
{
    int i = blockIdx.x * blockDim.x + threadIdx.x;
    if (i < NEDGE)               atomicAdd(&cntA[dstA[i]], 1);
    else if (i < 2 * NEDGE)      atomicAdd(&cntB[dstB[i - NEDGE]], 1);
}

// coarsened scan: 8 items/thread, block 0 = drug, block 1 = cell
__global__ void scan2_kernel(const int* __restrict__ cntA, int* __restrict__ offA,
                             const int* __restrict__ cntB, int* __restrict__ offB)
{
    const int* cnt = blockIdx.x == 0 ? cntA : cntB;
    int* off       = blockIdx.x == 0 ? offA : offB;
    const int n    = blockIdx.x == 0 ? NUM_DRUG : NUM_CELL;

    __shared__ int ws[32];
    __shared__ int s_carry;
    int t = threadIdx.x, lane = t & 31, w = t >> 5;
    if (t == 0) s_carry = 0;
    __syncthreads();

    for (int base = 0; base < n; base += 1024 * 8) {
        int idx = base + t * 8;
        int v[8];
        #pragma unroll
        for (int j = 0; j < 8; j++)
            v[j] = (idx + j < n) ? cnt[idx + j] : 0;
        #pragma unroll
        for (int j = 1; j < 8; j++) v[j] += v[j - 1];
        int tot = v[7];
        int x = tot;
        #pragma unroll
        for (int o = 1; o < 32; o <<= 1) {
            int y = __shfl_up_sync(0xffffffffu, x, o);
            if (lane >= o) x += y;
        }
        if (lane == 31) ws[w] = x;
        __syncthreads();
        if (w == 0) {
            int s = ws[lane];
            #pragma unroll
            for (int o = 1; o < 32; o <<= 1) {
                int y = __shfl_up_sync(0xffffffffu, s, o);
                if (lane >= o) s += y;
            }
            ws[lane] = s;
        }
        __syncthreads();
        int prefix = (x - tot) + (w ? ws[w - 1] : 0) + s_carry;
        #pragma unroll
        for (int j = 0; j < 8; j++)
            if (idx + j < n) off[idx + j + 1] = prefix + v[j];
        __syncthreads();
        if (t == 0) s_carry += ws[31];
        __syncthreads();
    }
    if (t == 0) off[0] = 0;
}

__global__ void fill2_kernel(const int* __restrict__ srcA, const int* __restrict__ dstA,
                             const int* __restrict__ offA, int* __restrict__ curA,
                             int* __restrict__ csrA,
                             const int* __restrict__ srcB, const int* __restrict__ dstB,
                             const int* __restrict__ offB, int* __restrict__ curB,
                             int* __restrict__ csrB)
{
    int i = blockIdx.x * blockDim.x + threadIdx.x;
    if (i < NEDGE) {
        int d = dstA[i];
        csrA[offA[d] + atomicAdd(&curA[d], 1)] = srcA[i];
    } else if (i < 2 * NEDGE) {
        int j = i - NEDGE;
        int d = dstB[j];
        csrB[offB[d] + atomicAdd(&curB[d], 1)] = srcB[j];
    }
}

__global__ void transpose2_kernel(const float* __restrict__ Wa, float* __restrict__ WTa,
                                  const float* __restrict__ Wb, float* __restrict__ WTb)
{
    int i = blockIdx.x * blockDim.x + threadIdx.x;
    int j = i & (HDIM * HDIM - 1);
    int k = j & 127, out = j >> 7;
    if (i < HDIM * HDIM) WTa[k * HDIM + out] = Wa[out * HDIM + k];
    else                 WTb[k * HDIM + out] = Wb[out * HDIM + k];
}

// ---------------- fp32 -> fp16 conversion of the two embedding tables ------
#define CONV_ELEMS ((NUM_DRUG + NUM_CELL) * HDIM)
__global__ void convert_kernel(const float* __restrict__ a, __half* __restrict__ ha,
                               const float* __restrict__ b, __half* __restrict__ hb)
{
    int i = blockIdx.x * blockDim.x + threadIdx.x;   // one float4 per thread
    const int na4 = NUM_DRUG * HDIM / 4;
    const int nb4 = NUM_CELL * HDIM / 4;
    if (i < na4) {
        float4 v = reinterpret_cast<const float4*>(a)[i];
        uint2 o;
        *reinterpret_cast<__half2*>(&o.x) = __floats2half2_rn(v.x, v.y);
        *reinterpret_cast<__half2*>(&o.y) = __floats2half2_rn(v.z, v.w);
        reinterpret_cast<uint2*>(ha)[i] = o;
    } else if (i < na4 + nb4) {
        int j = i - na4;
        float4 v = reinterpret_cast<const float4*>(b)[j];
        uint2 o;
        *reinterpret_cast<__half2*>(&o.x) = __floats2half2_rn(v.x, v.y);
        *reinterpret_cast<__half2*>(&o.y) = __floats2half2_rn(v.z, v.w);
        reinterpret_cast<uint2*>(hb)[j] = o;
    }
}

// ---------------- layer: fp16 gather-mean -> GEMM -> res -> LN -> ReLU -----
__global__ void __launch_bounds__(256, 2)
layer_kernel(const __half* __restrict__ srcD,  // fp16 gather table, drug rows
             const __half* __restrict__ srcC,  // fp16 gather table, cell rows
             const float* __restrict__ hd_in, const float* __restrict__ hc_in,
             float* __restrict__ hd_out, float* __restrict__ hc_out,
             __half* __restrict__ hd_out16, __half* __restrict__ hc_out16,
             const float* __restrict__ WT_td, const float* __restrict__ WT_dt,
             const float* __restrict__ gd, const float* __restrict__ bd,
             const float* __restrict__ gc, const float* __restrict__ bc,
             const int* __restrict__ off_d, const int* __restrict__ csr_d,
             const int* __restrict__ off_c, const int* __restrict__ csr_c)
{
    const bool isD = blockIdx.x < ND_BLOCKS;
    const __half* src  = isD ? srcC : srcD;    // messages come from other side
    const float* hold  = isD ? hd_in : hc_in;
    float* outp        = isD ? hd_out : hc_out;
    __half* outp16     = isD ? hd_out16 : hc_out16;
    const float* WTg   = isD ? WT_td : WT_dt;
    const float* gam   = isD ? gd : gc;
    const float* bet   = isD ? bd : bc;
    const int* off     = isD ? off_d : off_c;
    const int* csr     = isD ? csr_d : csr_c;
    const int ng8      = isD ? G8_DRUG : G8_CELL;
    const int nb       = isD ? ND_BLOCKS : (LAYER_BLOCKS - ND_BLOCKS);
    const int bid      = isD ? blockIdx.x : blockIdx.x - ND_BLOCKS;

    extern __shared__ float sm[];
    float* WT = sm;                                  // [128][128]
    const int t = threadIdx.x, lane = t & 31, w = t >> 5;
    float* XS = sm + HDIM * HDIM + w * (8 * HDIM);   // warp-private [8][128]
    const int c0 = 4 * lane;

    {
        const float4* s4 = reinterpret_cast<const float4*>(WTg);
        float4* d4 = reinterpret_cast<float4*>(WT);
        #pragma unroll
        for (int i = t; i < HDIM * HDIM / 4; i += 256) d4[i] = s4[i];
    }
    const float4 g4 = reinterpret_cast<const float4*>(gam)[lane];
    const float4 b4 = reinterpret_cast<const float4*>(bet)[lane];
    __syncthreads();

    const uint2* src2   = reinterpret_cast<const uint2*>(src);   // 32 uint2/row
    const float4* hold4 = reinterpret_cast<const float4*>(hold);
    float4* out4        = reinterpret_cast<float4*>(outp);
    uint2* out16        = reinterpret_cast<uint2*>(outp16);

    for (int wg = bid * WARPS + w; wg < ng8; wg += nb * WARPS) {
        const int row0 = wg * 8;

        // ---- gather-mean 8 rows into XS (fp16 source, fp32 accumulate) ----
        #pragma unroll
        for (int i = 0; i < 8; i++) {
            int r = row0 + i;
            int jb = off[r], je = off[r + 1];
            float4 a0 = {0,0,0,0}, a1 = {0,0,0,0}, a2 = {0,0,0,0}, a3 = {0,0,0,0};
            int j = jb;
            for (; j + 4 <= je; j += 4) {
                int s0 = csr[j], s1 = csr[j+1], s2 = csr[j+2], s3 = csr[j+3];
                uint2 v0 = src2[s0 * 32 + lane];
                uint2 v1 = src2[s1 * 32 + lane];
                uint2 v2 = src2[s2 * 32 + lane];
                uint2 v3 = src2[s3 * 32 + lane];
                acc_h4(a0, v0); acc_h4(a1, v1); acc_h4(a2, v2); acc_h4(a3, v3);
            }
            for (; j < je; j++) {
                uint2 v = src2[csr[j] * 32 + lane];
                acc_h4(a0, v);
            }
            a0.x += a1.x + a2.x + a3.x;
            a0.y += a1.y + a2.y + a3.y;
            a0.z += a1.z + a2.z + a3.z;
            a0.w += a1.w + a2.w + a3.w;
            int deg = je - jb;
            float inv = 1.0f / (float)(deg < 1 ? 1 : deg);
            a0.x *= inv; a0.y *= inv; a0.z *= inv; a0.w *= inv;
            *reinterpret_cast<float4*>(&XS[i * HDIM + c0]) = a0;
        }
        __syncwarp();

        // ---- GEMM: y[i][out] = sum_k x[i][k] * W[out][k], f32x2 packed ----
        unsigned long long acc2[8][2];
        #pragma unroll
        for (int i = 0; i < 8; i++) { acc2[i][0] = 0ull; acc2[i][1] = 0ull; }

        for (int kt = 0; kt < HDIM; kt += 4) {
            float4 xv[8];
            #pragma unroll
            for (int i = 0; i < 8; i++)
                xv[i] = *reinterpret_cast<const float4*>(&XS[i * HDIM + kt]);
            #pragma unroll
            for (int kk = 0; kk < 4; kk++) {
                ulonglong2 wv = *reinterpret_cast<const ulonglong2*>(
                    &WT[(kt + kk) * HDIM + c0]);
                #pragma unroll
                for (int i = 0; i < 8; i++) {
                    float xs = (kk == 0) ? xv[i].x : (kk == 1) ? xv[i].y
                             : (kk == 2) ? xv[i].z : xv[i].w;
                    unsigned long long s2 = splat2(xs);
                    acc2[i][0] = fma2(s2, wv.x, acc2[i][0]);
                    acc2[i][1] = fma2(s2, wv.y, acc2[i][1]);
                }
            }
        }

        // ---- epilogue: residual + LayerNorm + ReLU, fp32 + fp16 out ----
        #pragma unroll
        for (int i = 0; i < 8; i++) {
            int grow = row0 + i;
            float4 hv = hold4[grow * 32 + lane];
            float y0 = lo2(acc2[i][0]) + hv.x;
            float y1 = hi2(acc2[i][0]) + hv.y;
            float y2 = lo2(acc2[i][1]) + hv.z;
            float y3 = hi2(acc2[i][1]) + hv.w;

            float s = y0 + y1 + y2 + y3;
            float q = y0*y0 + y1*y1 + y2*y2 + y3*y3;
            #pragma unroll
            for (int o = 16; o; o >>= 1) {
                s += __shfl_xor_sync(0xffffffffu, s, o);
                q += __shfl_xor_sync(0xffffffffu, q, o);
            }
            float mu  = s * (1.0f / HDIM);
            float var = q * (1.0f / HDIM) - mu * mu;
            float rs  = rsqrtf(var + 1e-5f);
            float4 o4;
            o4.x = (y0 - mu) * rs * g4.x + b4.x; o4.x = o4.x > 0.f ? o4.x : 0.f;
            o4.y = (y1 - mu) * rs * g4.y + b4.y; o4.y = o4.y > 0.f ? o4.y : 0.f;
            o4.z = (y2 - mu) * rs * g4.z + b4.z; o4.z = o4.z > 0.f ? o4.z : 0.f;
            o4.w = (y3 - mu) * rs * g4.w + b4.w; o4.w = o4.w > 0.f ? o4.w : 0.f;
            out4[grow * 32 + lane] = o4;
            uint2 p;
            *reinterpret_cast<__half2*>(&p.x) = __floats2half2_rn(o4.x, o4.y);
            *reinterpret_cast<__half2*>(&p.y) = __floats2half2_rn(o4.z, o4.w);
            out16[grow * 32 + lane] = p;
        }
        __syncwarp();   // XS reused next iteration
    }
}

// ---------------- final head -------------------------------------------------
__global__ void final_kernel(const float* __restrict__ hd,
                             const float* __restrict__ hc,
                             const int* __restrict__ did,
                             const int* __restrict__ cid,
                             const float* __restrict__ wf,
                             const float* __restrict__ bf,
                             float* __restrict__ out, int nb)
{
    int warp = (blockIdx.x * blockDim.x + threadIdx.x) >> 5;
    int lane = threadIdx.x & 31;
    if (warp >= nb) return;
    int d = did[warp], c = cid[warp];
    float4 a  = reinterpret_cast<const float4*>(hd)[d * 32 + lane];
    float4 w1 = reinterpret_cast<const float4*>(wf)[lane];
    float4 b4 = reinterpret_cast<const float4*>(hc)[c * 32 + lane];
    float4 w2 = reinterpret_cast<const float4*>(wf)[32 + lane];
    float s = a.x * w1.x + a.y * w1.y + a.z * w1.z + a.w * w1.w
            + b4.x * w2.x + b4.y * w2.y + b4.z * w2.z + b4.w * w2.w;
    #pragma unroll
    for (int o = 16; o; o >>= 1) s += __shfl_xor_sync(0xffffffffu, s, o);
    if (lane == 0) {
        float x = s + bf[0];
        out[warp] = 1.0f / (1.0f + expf(-x));
    }
}

// ---------------------------------------------------------------------------
extern "C" void kernel_launch(void* const* d_in, const int* in_sizes, int n_in,
                              void* d_out, int out_size)
{
    const float* emb_drug  = (const float*)d_in[0];
    const float* emb_cell  = (const float*)d_in[1];
    const float* W_dt      = (const float*)d_in[2];
    const float* W_td      = (const float*)d_in[3];
    const float* ln_drug_g = (const float*)d_in[4];
    const float* ln_drug_b = (const float*)d_in[5];
    const float* ln_cell_g = (const float*)d_in[6];
    const float* ln_cell_b = (const float*)d_in[7];
    const float* W_final_w = (const float*)d_in[8];
    const float* W_final_b = (const float*)d_in[9];
    const int* edge_dt_src = (const int*)d_in[10];
    const int* edge_dt_dst = (const int*)d_in[11];
    const int* edge_td_src = (const int*)d_in[12];
    const int* edge_td_dst = (const int*)d_in[13];
    const int* drug_ids    = (const int*)d_in[14];
    const int* cell_ids    = (const int*)d_in[15];
    float* out = (float*)d_out;

    float *hA_d, *hA_c, *hB_d, *hB_c, *WT_td, *WT_dt;
    __half *he_d, *he_c, *h1_d, *h1_c;
    int *off_d, *off_c, *cur_d, *cur_c, *csr_td, *csr_dt;
    cudaGetSymbolAddress((void**)&hA_d,   g_hA_drug);
    cudaGetSymbolAddress((void**)&hA_c,   g_hA_cell);
    cudaGetSymbolAddress((void**)&hB_d,   g_hB_drug);
    cudaGetSymbolAddress((void**)&hB_c,   g_hB_cell);
    cudaGetSymbolAddress((void**)&he_d,   g_he_drug);
    cudaGetSymbolAddress((void**)&he_c,   g_he_cell);
    cudaGetSymbolAddress((void**)&h1_d,   g_h1_drug);
    cudaGetSymbolAddress((void**)&h1_c,   g_h1_cell);
    cudaGetSymbolAddress((void**)&WT_td,  g_WT_td);
    cudaGetSymbolAddress((void**)&WT_dt,  g_WT_dt);
    cudaGetSymbolAddress((void**)&off_d,  g_off_drug);
    cudaGetSymbolAddress((void**)&off_c,  g_off_cell);
    cudaGetSymbolAddress((void**)&cur_d,  g_cur_drug);
    cudaGetSymbolAddress((void**)&cur_c,  g_cur_cell);
    cudaGetSymbolAddress((void**)&csr_td, g_csr_td);
    cudaGetSymbolAddress((void**)&csr_dt, g_csr_dt);

    cudaFuncSetAttribute(layer_kernel,
                         cudaFuncAttributeMaxDynamicSharedMemorySize,
                         (int)LAYER_SMEM);

    const int eb2 = (2 * NEDGE + 255) / 256;

    // ---------------- CSR build + weight transpose + fp16 convert ----------
    cudaMemsetAsync(cur_d, 0, NUM_DRUG * sizeof(int));
    cudaMemsetAsync(cur_c, 0, NUM_CELL * sizeof(int));
    hist2_kernel<<<eb2, 256>>>(edge_td_dst, cur_d, edge_dt_dst, cur_c);
    convert_kernel<<<(CONV_ELEMS / 4 + 255) / 256, 256>>>(emb_drug, he_d, emb_cell, he_c);
    scan2_kernel<<<2, 1024>>>(cur_d, off_d, cur_c, off_c);
    cudaMemsetAsync(cur_d, 0, NUM_DRUG * sizeof(int));
    cudaMemsetAsync(cur_c, 0, NUM_CELL * sizeof(int));
    fill2_kernel<<<eb2, 256>>>(edge_td_src, edge_td_dst, off_d, cur_d, csr_td,
                               edge_dt_src, edge_dt_dst, off_c, cur_c, csr_dt);
    transpose2_kernel<<<2 * HDIM * HDIM / 256, 256>>>(W_td, WT_td, W_dt, WT_dt);

    // ---------------- layers ----------------
    // layer 0: gather from converted emb tables, write hA (fp32) + h1 (fp16)
    layer_kernel<<<LAYER_BLOCKS, 256, LAYER_SMEM>>>(
        he_d, he_c, emb_drug, emb_cell, hA_d, hA_c, h1_d, h1_c,
        WT_td, WT_dt, ln_drug_g, ln_drug_b, ln_cell_g, ln_cell_b,
        off_d, csr_td, off_c, csr_dt);
    // layer 1: gather from h1 tables, write hB (fp32) + he (fp16, reused/unused)
    layer_kernel<<<LAYER_BLOCKS, 256, LAYER_SMEM>>>(
        h1_d, h1_c, hA_d, hA_c, hB_d, hB_c, he_d, he_c,
        WT_td, WT_dt, ln_drug_g, ln_drug_b, ln_cell_g, ln_cell_b,
        off_d, csr_td, off_c, csr_dt);

    // ---------------- final head ----------------
    final_kernel<<<(NBATCH * 32) / 256, 256>>>(hB_d, hB_c, drug_ids, cell_ids,
                                               W_final_w, W_final_b, out, NBATCH);
}

// round 5
// speedup vs baseline: 1.1902x; 1.1902x over previous
#include <cuda_runtime.h>

#define NUM_DRUG 50000
#define NUM_CELL 20000
#define HDIM     128
#define NEDGE    600000
#define NBATCH   4096

#define G8_DRUG (NUM_DRUG / 8)   // 6250 warp-groups (divides exactly)
#define G8_CELL (NUM_CELL / 8)   // 2500

#define LAYER_BLOCKS 296
#define ND_BLOCKS    172         // blocks assigned to the drug side
#define WARPS        8           // 256 threads / block
#define LAYER_SMEM ((HDIM * HDIM + WARPS * 8 * HDIM) * sizeof(float))  // 96 KB

// ---------------- scratch (device globals; no runtime allocation) ----------
__device__ __align__(16) float g_hA_drug[NUM_DRUG * HDIM];
__device__ __align__(16) float g_hA_cell[NUM_CELL * HDIM];
__device__ __align__(16) float g_hB_drug[NUM_DRUG * HDIM];
__device__ __align__(16) float g_hB_cell[NUM_CELL * HDIM];
__device__ __align__(16) float g_WT_td[HDIM * HDIM];
__device__ __align__(16) float g_WT_dt[HDIM * HDIM];
__device__ int g_off_drug[NUM_DRUG + 1];
__device__ int g_off_cell[NUM_CELL + 1];
__device__ int g_cur_drug[NUM_DRUG];
__device__ int g_cur_cell[NUM_CELL];
__device__ int g_csr_td[NEDGE];   // per drug-dst: source cell ids
__device__ int g_csr_dt[NEDGE];   // per cell-dst: source drug ids

// ---------------- f32x2 helpers --------------------------------------------
__device__ __forceinline__ unsigned long long splat2(float x) {
    unsigned long long r; unsigned xi = __float_as_uint(x);
    asm("mov.b64 %0, {%1, %1};" : "=l"(r) : "r"(xi));
    return r;
}
__device__ __forceinline__ unsigned long long fma2(unsigned long long a,
                                                   unsigned long long b,
                                                   unsigned long long c) {
    unsigned long long d;
    asm("fma.rn.f32x2 %0, %1, %2, %3;" : "=l"(d) : "l"(a), "l"(b), "l"(c));
    return d;
}
__device__ __forceinline__ float lo2(unsigned long long v) {
    return __uint_as_float((unsigned)(v & 0xffffffffull));
}
__device__ __forceinline__ float hi2(unsigned long long v) {
    return __uint_as_float((unsigned)(v >> 32));
}

// ---------------- CSR build -------------------------------------------------
__global__ void hist2_kernel(const int* __restrict__ dstA, int* __restrict__ cntA,
                             const int* __restrict__ dstB, int* __restrict__ cntB)
{
    int i = blockIdx.x * blockDim.x + threadIdx.x;
    if (i < NEDGE)               atomicAdd(&cntA[dstA[i]], 1);
    else if (i < 2 * NEDGE)      atomicAdd(&cntB[dstB[i - NEDGE]], 1);
}

// blocks 0,1: coarsened scans (drug / cell). blocks 2,3: weight transposes.
__global__ void scan_transpose_kernel(const int* __restrict__ cntA, int* __restrict__ offA,
                                      const int* __restrict__ cntB, int* __restrict__ offB,
                                      const float* __restrict__ Wa, float* __restrict__ WTa,
                                      const float* __restrict__ Wb, float* __restrict__ WTb)
{
    int t = threadIdx.x;
    if (blockIdx.x >= 2) {
        const float* W = blockIdx.x == 2 ? Wa : Wb;
        float* WT      = blockIdx.x == 2 ? WTa : WTb;
        #pragma unroll
        for (int i = t; i < HDIM * HDIM; i += 1024) {
            int k = i & 127, out = i >> 7;
            WT[k * HDIM + out] = W[out * HDIM + k];
        }
        return;
    }
    const int* cnt = blockIdx.x == 0 ? cntA : cntB;
    int* off       = blockIdx.x == 0 ? offA : offB;
    const int n    = blockIdx.x == 0 ? NUM_DRUG : NUM_CELL;

    __shared__ int ws[32];
    __shared__ int s_carry;
    int lane = t & 31, w = t >> 5;
    if (t == 0) s_carry = 0;
    __syncthreads();

    for (int base = 0; base < n; base += 1024 * 8) {
        int idx = base + t * 8;
        int v[8];
        #pragma unroll
        for (int j = 0; j < 8; j++)
            v[j] = (idx + j < n) ? cnt[idx + j] : 0;
        #pragma unroll
        for (int j = 1; j < 8; j++) v[j] += v[j - 1];
        int tot = v[7];
        int x = tot;
        #pragma unroll
        for (int o = 1; o < 32; o <<= 1) {
            int y = __shfl_up_sync(0xffffffffu, x, o);
            if (lane >= o) x += y;
        }
        if (lane == 31) ws[w] = x;
        __syncthreads();
        if (w == 0) {
            int s = ws[lane];
            #pragma unroll
            for (int o = 1; o < 32; o <<= 1) {
                int y = __shfl_up_sync(0xffffffffu, s, o);
                if (lane >= o) s += y;
            }
            ws[lane] = s;
        }
        __syncthreads();
        int prefix = (x - tot) + (w ? ws[w - 1] : 0) + s_carry;
        #pragma unroll
        for (int j = 0; j < 8; j++)
            if (idx + j < n) off[idx + j + 1] = prefix + v[j];
        __syncthreads();
        if (t == 0) s_carry += ws[31];
        __syncthreads();
    }
    if (t == 0) off[0] = 0;
}

// 2 independent edges per thread for latency hiding
__global__ void fill2_kernel(const int* __restrict__ srcA, const int* __restrict__ dstA,
                             const int* __restrict__ offA, int* __restrict__ curA,
                             int* __restrict__ csrA,
                             const int* __restrict__ srcB, const int* __restrict__ dstB,
                             const int* __restrict__ offB, int* __restrict__ curB,
                             int* __restrict__ csrB)
{
    int tid = blockIdx.x * blockDim.x + threadIdx.x;
    int i0 = tid * 2;
    if (i0 < NEDGE) {
        int i1 = i0 + 1;
        int d0 = dstA[i0];
        int d1 = (i1 < NEDGE) ? dstA[i1] : -1;
        int s0 = srcA[i0];
        int s1 = (i1 < NEDGE) ? srcA[i1] : 0;
        int p0 = offA[d0] + atomicAdd(&curA[d0], 1);
        int p1 = (d1 >= 0) ? (offA[d1] + atomicAdd(&curA[d1], 1)) : 0;
        csrA[p0] = s0;
        if (d1 >= 0) csrA[p1] = s1;
    } else if (i0 < 2 * NEDGE) {
        int j0 = i0 - NEDGE, j1 = j0 + 1;
        int d0 = dstB[j0];
        int d1 = (j1 < NEDGE) ? dstB[j1] : -1;
        int s0 = srcB[j0];
        int s1 = (j1 < NEDGE) ? srcB[j1] : 0;
        int p0 = offB[d0] + atomicAdd(&curB[d0], 1);
        int p1 = (d1 >= 0) ? (offB[d1] + atomicAdd(&curB[d1], 1)) : 0;
        csrB[p0] = s0;
        if (d1 >= 0) csrB[p1] = s1;
    }
}

// ---------------- layer: gather-mean -> GEMM -> residual -> LN -> ReLU -----
__global__ void __launch_bounds__(256, 2)
layer_kernel(const float* __restrict__ hd_in, const float* __restrict__ hc_in,
             float* __restrict__ hd_out, float* __restrict__ hc_out,
             const float* __restrict__ WT_td, const float* __restrict__ WT_dt,
             const float* __restrict__ gd, const float* __restrict__ bd,
             const float* __restrict__ gc, const float* __restrict__ bc,
             const int* __restrict__ off_d, const int* __restrict__ csr_d,
             const int* __restrict__ off_c, const int* __restrict__ csr_c)
{
    const bool isD = blockIdx.x < ND_BLOCKS;
    const float* src  = isD ? hc_in : hd_in;   // gather messages from other side
    const float* hold = isD ? hd_in : hc_in;
    float* outp       = isD ? hd_out : hc_out;
    const float* WTg  = isD ? WT_td : WT_dt;
    const float* gam  = isD ? gd : gc;
    const float* bet  = isD ? bd : bc;
    const int* off    = isD ? off_d : off_c;
    const int* csr    = isD ? csr_d : csr_c;
    const int ng8     = isD ? G8_DRUG : G8_CELL;
    const int nb      = isD ? ND_BLOCKS : (LAYER_BLOCKS - ND_BLOCKS);
    const int bid     = isD ? blockIdx.x : blockIdx.x - ND_BLOCKS;

    extern __shared__ float sm[];
    float* WT = sm;                                  // [128][128]
    const int t = threadIdx.x, lane = t & 31, w = t >> 5;
    float* XS = sm + HDIM * HDIM + w * (8 * HDIM);   // warp-private [8][128]
    const int c0 = 4 * lane;

    {
        const float4* s4 = reinterpret_cast<const float4*>(WTg);
        float4* d4 = reinterpret_cast<float4*>(WT);
        #pragma unroll
        for (int i = t; i < HDIM * HDIM / 4; i += 256) d4[i] = s4[i];
    }
    const float4 g4 = reinterpret_cast<const float4*>(gam)[lane];
    const float4 b4 = reinterpret_cast<const float4*>(bet)[lane];
    __syncthreads();

    const float4* src4  = reinterpret_cast<const float4*>(src);
    const float4* hold4 = reinterpret_cast<const float4*>(hold);
    float4* out4        = reinterpret_cast<float4*>(outp);

    for (int wg = bid * WARPS + w; wg < ng8; wg += nb * WARPS) {
        const int row0 = wg * 8;

        // ---- gather-mean 8 rows into XS ----
        #pragma unroll
        for (int i = 0; i < 8; i++) {
            int r = row0 + i;
            int jb = off[r], je = off[r + 1];
            float4 a0 = {0,0,0,0}, a1 = {0,0,0,0}, a2 = {0,0,0,0}, a3 = {0,0,0,0};
            int j = jb;
            for (; j + 4 <= je; j += 4) {
                int s0 = csr[j], s1 = csr[j+1], s2 = csr[j+2], s3 = csr[j+3];
                float4 v0 = src4[s0 * 32 + lane];
                float4 v1 = src4[s1 * 32 + lane];
                float4 v2 = src4[s2 * 32 + lane];
                float4 v3 = src4[s3 * 32 + lane];
                a0.x += v0.x; a0.y += v0.y; a0.z += v0.z; a0.w += v0.w;
                a1.x += v1.x; a1.y += v1.y; a1.z += v1.z; a1.w += v1.w;
                a2.x += v2.x; a2.y += v2.y; a2.z += v2.z; a2.w += v2.w;
                a3.x += v3.x; a3.y += v3.y; a3.z += v3.z; a3.w += v3.w;
            }
            for (; j < je; j++) {
                float4 v = src4[csr[j] * 32 + lane];
                a0.x += v.x; a0.y += v.y; a0.z += v.z; a0.w += v.w;
            }
            a0.x += a1.x + a2.x + a3.x;
            a0.y += a1.y + a2.y + a3.y;
            a0.z += a1.z + a2.z + a3.z;
            a0.w += a1.w + a2.w + a3.w;
            int deg = je - jb;
            float inv = 1.0f / (float)(deg < 1 ? 1 : deg);
            a0.x *= inv; a0.y *= inv; a0.z *= inv; a0.w *= inv;
            *reinterpret_cast<float4*>(&XS[i * HDIM + c0]) = a0;
        }
        __syncwarp();

        // ---- GEMM: y[i][out] = sum_k x[i][k] * W[out][k], f32x2 packed ----
        unsigned long long acc2[8][2];
        #pragma unroll
        for (int i = 0; i < 8; i++) { acc2[i][0] = 0ull; acc2[i][1] = 0ull; }

        for (int kt = 0; kt < HDIM; kt += 4) {
            float4 xv[8];
            #pragma unroll
            for (int i = 0; i < 8; i++)
                xv[i] = *reinterpret_cast<const float4*>(&XS[i * HDIM + kt]);
            #pragma unroll
            for (int kk = 0; kk < 4; kk++) {
                ulonglong2 wv = *reinterpret_cast<const ulonglong2*>(
                    &WT[(kt + kk) * HDIM + c0]);
                #pragma unroll
                for (int i = 0; i < 8; i++) {
                    float xs = (kk == 0) ? xv[i].x : (kk == 1) ? xv[i].y
                             : (kk == 2) ? xv[i].z : xv[i].w;
                    unsigned long long s2 = splat2(xs);
                    acc2[i][0] = fma2(s2, wv.x, acc2[i][0]);
                    acc2[i][1] = fma2(s2, wv.y, acc2[i][1]);
                }
            }
        }

        // ---- epilogue: residual + LayerNorm + ReLU ----
        #pragma unroll
        for (int i = 0; i < 8; i++) {
            int grow = row0 + i;
            float4 hv = hold4[grow * 32 + lane];
            float y0 = lo2(acc2[i][0]) + hv.x;
            float y1 = hi2(acc2[i][0]) + hv.y;
            float y2 = lo2(acc2[i][1]) + hv.z;
            float y3 = hi2(acc2[i][1]) + hv.w;

            float s = y0 + y1 + y2 + y3;
            float q = y0*y0 + y1*y1 + y2*y2 + y3*y3;
            #pragma unroll
            for (int o = 16; o; o >>= 1) {
                s += __shfl_xor_sync(0xffffffffu, s, o);
                q += __shfl_xor_sync(0xffffffffu, q, o);
            }
            float mu  = s * (1.0f / HDIM);
            float var = q * (1.0f / HDIM) - mu * mu;
            float rs  = rsqrtf(var + 1e-5f);
            float4 o4;
            o4.x = (y0 - mu) * rs * g4.x + b4.x; o4.x = o4.x > 0.f ? o4.x : 0.f;
            o4.y = (y1 - mu) * rs * g4.y + b4.y; o4.y = o4.y > 0.f ? o4.y : 0.f;
            o4.z = (y2 - mu) * rs * g4.z + b4.z; o4.z = o4.z > 0.f ? o4.z : 0.f;
            o4.w = (y3 - mu) * rs * g4.w + b4.w; o4.w = o4.w > 0.f ? o4.w : 0.f;
            out4[grow * 32 + lane] = o4;
        }
        __syncwarp();   // XS reused next iteration
    }
}

// ---------------- final head -------------------------------------------------
__global__ void final_kernel(const float* __restrict__ hd,
                             const float* __restrict__ hc,
                             const int* __restrict__ did,
                             const int* __restrict__ cid,
                             const float* __restrict__ wf,
                             const float* __restrict__ bf,
                             float* __restrict__ out, int nb)
{
    int warp = (blockIdx.x * blockDim.x + threadIdx.x) >> 5;
    int lane = threadIdx.x & 31;
    if (warp >= nb) return;
    int d = did[warp], c = cid[warp];
    float4 a  = reinterpret_cast<const float4*>(hd)[d * 32 + lane];
    float4 w1 = reinterpret_cast<const float4*>(wf)[lane];
    float4 b4 = reinterpret_cast<const float4*>(hc)[c * 32 + lane];
    float4 w2 = reinterpret_cast<const float4*>(wf)[32 + lane];
    float s = a.x * w1.x + a.y * w1.y + a.z * w1.z + a.w * w1.w
            + b4.x * w2.x + b4.y * w2.y + b4.z * w2.z + b4.w * w2.w;
    #pragma unroll
    for (int o = 16; o; o >>= 1) s += __shfl_xor_sync(0xffffffffu, s, o);
    if (lane == 0) {
        float x = s + bf[0];
        out[warp] = 1.0f / (1.0f + expf(-x));
    }
}

// ---------------------------------------------------------------------------
extern "C" void kernel_launch(void* const* d_in, const int* in_sizes, int n_in,
                              void* d_out, int out_size)
{
    const float* emb_drug  = (const float*)d_in[0];
    const float* emb_cell  = (const float*)d_in[1];
    const float* W_dt      = (const float*)d_in[2];
    const float* W_td      = (const float*)d_in[3];
    const float* ln_drug_g = (const float*)d_in[4];
    const float* ln_drug_b = (const float*)d_in[5];
    const float* ln_cell_g = (const float*)d_in[6];
    const float* ln_cell_b = (const float*)d_in[7];
    const float* W_final_w = (const float*)d_in[8];
    const float* W_final_b = (const float*)d_in[9];
    const int* edge_dt_src = (const int*)d_in[10];
    const int* edge_dt_dst = (const int*)d_in[11];
    const int* edge_td_src = (const int*)d_in[12];
    const int* edge_td_dst = (const int*)d_in[13];
    const int* drug_ids    = (const int*)d_in[14];
    const int* cell_ids    = (const int*)d_in[15];
    float* out = (float*)d_out;

    float *hA_d, *hA_c, *hB_d, *hB_c, *WT_td, *WT_dt;
    int *off_d, *off_c, *cur_d, *cur_c, *csr_td, *csr_dt;
    cudaGetSymbolAddress((void**)&hA_d,   g_hA_drug);
    cudaGetSymbolAddress((void**)&hA_c,   g_hA_cell);
    cudaGetSymbolAddress((void**)&hB_d,   g_hB_drug);
    cudaGetSymbolAddress((void**)&hB_c,   g_hB_cell);
    cudaGetSymbolAddress((void**)&WT_td,  g_WT_td);
    cudaGetSymbolAddress((void**)&WT_dt,  g_WT_dt);
    cudaGetSymbolAddress((void**)&off_d,  g_off_drug);
    cudaGetSymbolAddress((void**)&off_c,  g_off_cell);
    cudaGetSymbolAddress((void**)&cur_d,  g_cur_drug);
    cudaGetSymbolAddress((void**)&cur_c,  g_cur_cell);
    cudaGetSymbolAddress((void**)&csr_td, g_csr_td);
    cudaGetSymbolAddress((void**)&csr_dt, g_csr_dt);

    cudaFuncSetAttribute(layer_kernel,
                         cudaFuncAttributeMaxDynamicSharedMemorySize,
                         (int)LAYER_SMEM);

    const int eb2 = (2 * NEDGE + 255) / 256;

    // ---------------- CSR build (layer_kernel is the 4th non-memset launch) ----
    cudaMemsetAsync(cur_d, 0, NUM_DRUG * sizeof(int));
    cudaMemsetAsync(cur_c, 0, NUM_CELL * sizeof(int));
    hist2_kernel<<<eb2, 256>>>(edge_td_dst, cur_d, edge_dt_dst, cur_c);          // (1)
    scan_transpose_kernel<<<4, 1024>>>(cur_d, off_d, cur_c, off_c,
                                       W_td, WT_td, W_dt, WT_dt);                 // (2)
    cudaMemsetAsync(cur_d, 0, NUM_DRUG * sizeof(int));
    cudaMemsetAsync(cur_c, 0, NUM_CELL * sizeof(int));
    fill2_kernel<<<(NEDGE + 255) / 256, 256>>>(                                   // (3)
        edge_td_src, edge_td_dst, off_d, cur_d, csr_td,
        edge_dt_src, edge_dt_dst, off_c, cur_c, csr_dt);

    // ---------------- layers ----------------
    layer_kernel<<<LAYER_BLOCKS, 256, LAYER_SMEM>>>(                              // (4) <- ncu
        emb_drug, emb_cell, hA_d, hA_c, WT_td, WT_dt,
        ln_drug_g, ln_drug_b, ln_cell_g, ln_cell_b,
        off_d, csr_td, off_c, csr_dt);
    layer_kernel<<<LAYER_BLOCKS, 256, LAYER_SMEM>>>(
        hA_d, hA_c, hB_d, hB_c, WT_td, WT_dt,
        ln_drug_g, ln_drug_b, ln_cell_g, ln_cell_b,
        off_d, csr_td, off_c, csr_dt);

    // ---------------- final head ----------------
    final_kernel<<<(NBATCH * 32) / 256, 256>>>(hB_d, hB_c, drug_ids, cell_ids,
                                               W_final_w, W_final_b, out, NBATCH);
}